// round 7
// baseline (speedup 1.0000x reference)
#include <cuda_runtime.h>

// WaveletMask: fused Haar fwd -> mosaic weight multiply -> Haar inv.
// H=128, HB=64. One thread per 2x2 spatial block => 4096 threads.
// Best measured geometry: 32 blocks x 128 threads (R1 config, kernel 3.968us).
// Per thread: 2x LDG.64 (x), 4x LDG.32 (w), 2x STG.64 (out). All independent.

#define H 128
#define HB 64

__global__ void __launch_bounds__(128, 1) wavelet_mask_kernel(
    const float* __restrict__ x,
    const float* __restrict__ w,
    float* __restrict__ out)
{
    const int t = blockIdx.x * 128 + threadIdx.x;  // 0..4095
    const int i = t >> 6;          // block row 0..63
    const int j = t & 63;          // block col 0..63

    const int xoff = (i << 8) + (j << 1);          // 2i*H + 2j  (H=128)
    const int woff = (i << 7) + j;                 // i*H + j

    // Vectorized loads of the 2x2 input block
    const float2 top = *reinterpret_cast<const float2*>(x + xoff);
    const float2 bot = *reinterpret_cast<const float2*>(x + xoff + H);
    const float a = top.x, b = top.y, c = bot.x, d = bot.y;

    // Mosaic weights: LL / LH / HL / HH quadrants (non-coherent path)
    const float wll = __ldg(w + woff);
    const float wlh = __ldg(w + woff + HB);
    const float whl = __ldg(w + woff + HB * H);
    const float whh = __ldg(w + woff + HB * H + HB);

    // Forward Haar (orthonormal) * weight
    const float apb = a + b, amb = a - b, cpd = c + d, cmd = c - d;
    const float ll = (apb + cpd) * 0.5f * wll;
    const float lh = (apb - cpd) * 0.5f * wlh;
    const float hl = (amb + cmd) * 0.5f * whl;
    const float hh = (amb - cmd) * 0.5f * whh;

    // Inverse Haar
    const float lplh = ll + lh, lmlh = ll - lh;
    const float hphh = hl + hh, hmhh = hl - hh;
    float2 otop, obot;
    otop.x = (lplh + hphh) * 0.5f;   // a'
    otop.y = (lplh - hphh) * 0.5f;   // b'
    obot.x = (lmlh + hmhh) * 0.5f;   // c'
    obot.y = (lmlh - hmhh) * 0.5f;   // d'

    *reinterpret_cast<float2*>(out + xoff)     = otop;
    *reinterpret_cast<float2*>(out + xoff + H) = obot;
}

extern "C" void kernel_launch(void* const* d_in, const int* in_sizes, int n_in,
                              void* d_out, int out_size)
{
    const float* x = (const float*)d_in[0];
    const float* w = (const float*)d_in[1];
    float* out = (float*)d_out;
    wavelet_mask_kernel<<<32, 128>>>(x, w, out);
}

// round 8
// speedup vs baseline: 1.5105x; 1.5105x over previous
#include <cuda_runtime.h>

// WaveletMask: fused Haar fwd -> mosaic weight multiply -> Haar inv.
// H=128, HB=64. One thread per 2x2 spatial block => 4096 threads total.
// Each thread: 2x float2 loads (x), 4x float loads (weight), 2x float2 stores.
// Geometry 32 blocks x 128 threads: best measured (kernel 3.968us, e2e 4.608us).

#define H 128
#define HB 64

__global__ void __launch_bounds__(128, 1) wavelet_mask_kernel(
    const float* __restrict__ x,
    const float* __restrict__ w,
    float* __restrict__ out)
{
    const int t = blockIdx.x * blockDim.x + threadIdx.x;   // 0..4095
    const int i = t >> 6;          // block row 0..63
    const int j = t & 63;          // block col 0..63

    // Vectorized loads of the 2x2 input block
    const float2 top = *reinterpret_cast<const float2*>(x + (2 * i) * H + 2 * j);
    const float2 bot = *reinterpret_cast<const float2*>(x + (2 * i + 1) * H + 2 * j);
    const float a = top.x, b = top.y, c = bot.x, d = bot.y;

    // Mosaic weights: LL / LH / HL / HH quadrants
    const float wll = w[i * H + j];
    const float wlh = w[i * H + j + HB];
    const float whl = w[(i + HB) * H + j];
    const float whh = w[(i + HB) * H + j + HB];

    // Forward Haar (orthonormal) * weight
    const float apb = a + b, amb = a - b, cpd = c + d, cmd = c - d;
    const float ll = (apb + cpd) * 0.5f * wll;
    const float lh = (apb - cpd) * 0.5f * wlh;
    const float hl = (amb + cmd) * 0.5f * whl;
    const float hh = (amb - cmd) * 0.5f * whh;

    // Inverse Haar
    const float lplh = ll + lh, lmlh = ll - lh;
    const float hphh = hl + hh, hmhh = hl - hh;
    float2 otop, obot;
    otop.x = (lplh + hphh) * 0.5f;   // a'
    otop.y = (lplh - hphh) * 0.5f;   // b'
    obot.x = (lmlh + hmhh) * 0.5f;   // c'
    obot.y = (lmlh - hmhh) * 0.5f;   // d'

    *reinterpret_cast<float2*>(out + (2 * i) * H + 2 * j)     = otop;
    *reinterpret_cast<float2*>(out + (2 * i + 1) * H + 2 * j) = obot;
}

extern "C" void kernel_launch(void* const* d_in, const int* in_sizes, int n_in,
                              void* d_out, int out_size)
{
    const float* x = (const float*)d_in[0];
    const float* w = (const float*)d_in[1];
    float* out = (float*)d_out;
    // 4096 threads total: 32 blocks x 128 threads, spread across SMs
    wavelet_mask_kernel<<<32, 128>>>(x, w, out);
}